// round 4
// baseline (speedup 1.0000x reference)
#include <cuda_runtime.h>
#include <cstdint>

#define NTOK 8192
#define HDIM 1024
#define FDIM 4096
#define NEXP 8

#define BM 128
#define BN 256
#define BK 32
#define NSTAGE 4

// SMEM layout (bytes). Rows padded to 36 floats (144B) for conflict-free LDSM.
#define ROW_B 144
#define A_STAGE (BM * ROW_B)            /* 18432 */
#define B_STAGE (BN * ROW_B)            /* 36864 */
#define OFF_TOK  0
#define OFF_WGT  512
#define OFF_BIAS 1024
#define OFF_A    2048
#define OFF_B    (OFF_A + NSTAGE * A_STAGE)                 /* 75776 */
#define SMEM_TOTAL (OFF_B + NSTAGE * B_STAGE)               /* 223232 */

// ---------------- scratch (device globals: no allocation allowed) ----------
__device__ int   g_cnt[NEXP];
__device__ int   g_off[NEXP];
__device__ int   g_tok[NEXP * NTOK];
__device__ float g_wgt[NEXP * NTOK];
__device__ float g_hbuf[(size_t)(2 * NTOK) * FDIM];            // 256 MB (tf32-rounded)
__device__ float g_xr  [(size_t)NTOK * HDIM];                  // 32 MB  (tf32-rounded x)
__device__ float g_w1t [(size_t)NEXP * (size_t)HDIM * FDIM];   // rounded W1^T, [e][f][h]
__device__ float g_w2t [(size_t)NEXP * (size_t)FDIM * HDIM];   // rounded W2^T, [e][h][f]

// ---------------- helpers ---------------------------------------------------
__device__ __forceinline__ uint32_t smem_u32(const void* p) {
    uint32_t a;
    asm("{ .reg .u64 t; cvta.to.shared.u64 t, %1; cvt.u32.u64 %0, t; }" : "=r"(a) : "l"(p));
    return a;
}

__device__ __forceinline__ float tf32r(float x) {
    uint32_t u;
    asm("cvt.rna.tf32.f32 %0, %1;" : "=r"(u) : "f"(x));
    return __uint_as_float(u);
}

__device__ __forceinline__ void mma_tf32(float* c, const uint32_t* a, const uint32_t* b) {
    asm("mma.sync.aligned.m16n8k8.row.col.f32.tf32.tf32.f32 "
        "{%0,%1,%2,%3}, {%4,%5,%6,%7}, {%8,%9}, {%0,%1,%2,%3};"
        : "+f"(c[0]), "+f"(c[1]), "+f"(c[2]), "+f"(c[3])
        : "r"(a[0]), "r"(a[1]), "r"(a[2]), "r"(a[3]),
          "r"(b[0]), "r"(b[1]));
}

#define LDSM4(r0, r1, r2, r3, addr) \
    asm volatile("ldmatrix.sync.aligned.m8n8.x4.shared.b16 {%0,%1,%2,%3}, [%4];" \
                 : "=r"(r0), "=r"(r1), "=r"(r2), "=r"(r3) : "r"(addr))

__device__ __forceinline__ float gelu_exact(float v) {
    return 0.5f * v * (1.0f + erff(v * 0.70710678118654752440f));
}

#define CP16(dst, src) \
    asm volatile("cp.async.cg.shared.global [%0], [%1], 16;" \
                 :: "r"((uint32_t)(dst)), "l"(__cvta_generic_to_global(src)))
#define CP_COMMIT() asm volatile("cp.async.commit_group;" ::: "memory")

// ---------------- kernel: zero out + counters -------------------------------
__global__ void zero_kernel(float4* out, int nf4) {
    int i = blockIdx.x * 256 + threadIdx.x;
    if (i < nf4) out[i] = make_float4(0.f, 0.f, 0.f, 0.f);
    if (i < NEXP) g_cnt[i] = 0;
}

// ---------------- kernel: tf32-round x ---------------------------------------
__global__ void round_kernel(const float4* __restrict__ src, float4* __restrict__ dst) {
    size_t i = (size_t)blockIdx.x * 256 + threadIdx.x;
    float4 v = src[i];
    v.x = tf32r(v.x); v.y = tf32r(v.y); v.z = tf32r(v.z); v.w = tf32r(v.w);
    dst[i] = v;
}

// ---------------- kernel: transpose + tf32-round weights --------------------
// src[e][r][c] (c contiguous) -> dst[e][c][r]
__global__ void transpose_kernel(const float* __restrict__ src, int R, int C, int which) {
    __shared__ float t[32][33];
    float* dstg = which ? g_w2t : g_w1t;
    int e = blockIdx.z;
    int c0 = blockIdx.x * 32, r0 = blockIdx.y * 32;
    const float* s = src + (size_t)e * R * C;
    float* d = dstg + (size_t)e * R * C;
    int tx = threadIdx.x & 31, ty = threadIdx.x >> 5;   // 32 x 8
    #pragma unroll
    for (int i = 0; i < 4; i++) {
        int r = r0 + ty + i * 8;
        t[ty + i * 8][tx] = tf32r(s[(size_t)r * C + c0 + tx]);
    }
    __syncthreads();
    #pragma unroll
    for (int i = 0; i < 4; i++) {
        int c = c0 + ty + i * 8;
        d[(size_t)c * R + r0 + tx] = t[tx][ty + i * 8];
    }
}

// ---------------- kernel: router (one warp per token) -----------------------
__global__ void router_kernel(const float* __restrict__ x,
                              const float* __restrict__ grad,
                              const float* __restrict__ Wr,
                              const float* __restrict__ br) {
    int n = blockIdx.x * 8 + (threadIdx.x >> 5);
    int lane = threadIdx.x & 31;
    if (n >= NTOK) return;

    float acc[NEXP];
    #pragma unroll
    for (int e = 0; e < NEXP; e++) acc[e] = 0.f;

    const float* xr = x + (size_t)n * HDIM;
    for (int h = lane; h < HDIM; h += 32) {
        float xv = xr[h];
        const float* wrow = Wr + h * NEXP;
        #pragma unroll
        for (int e = 0; e < NEXP; e++) acc[e] = fmaf(xv, wrow[e], acc[e]);
    }
    #pragma unroll
    for (int e = 0; e < NEXP; e++) {
        #pragma unroll
        for (int off = 16; off > 0; off >>= 1)
            acc[e] += __shfl_xor_sync(0xffffffffu, acc[e], off);
    }
    if (lane == 0) {
        float gv = grad[n];
        float l[NEXP];
        #pragma unroll
        for (int e = 0; e < NEXP; e++)
            l[e] = acc[e] + gv * Wr[HDIM * NEXP + e] + br[e];
        float m = l[0];
        #pragma unroll
        for (int e = 1; e < NEXP; e++) m = fmaxf(m, l[e]);
        float p[NEXP];
        float s = 0.f;
        #pragma unroll
        for (int e = 0; e < NEXP; e++) { p[e] = expf(l[e] - m); s += p[e]; }
        float inv = 1.f / s;
        int i1 = 0;
        #pragma unroll
        for (int e = 1; e < NEXP; e++) if (p[e] > p[i1]) i1 = e;
        int i2 = (i1 == 0) ? 1 : 0;
        #pragma unroll
        for (int e = 0; e < NEXP; e++) if (e != i1 && p[e] > p[i2]) i2 = e;

        int s1 = atomicAdd(&g_cnt[i1], 1);
        g_tok[i1 * NTOK + s1] = n;  g_wgt[i1 * NTOK + s1] = p[i1] * inv;
        int s2 = atomicAdd(&g_cnt[i2], 1);
        g_tok[i2 * NTOK + s2] = n;  g_wgt[i2 * NTOK + s2] = p[i2] * inv;
    }
}

__global__ void prefix_kernel() {
    if (threadIdx.x == 0) {
        int s = 0;
        #pragma unroll
        for (int e = 0; e < NEXP; e++) { g_off[e] = s; s += g_cnt[e]; }
    }
}

// ---------------- pipelined grouped GEMM (HMMA tf32 + LDSM fragments) --------
// A[BM,KDIM] k-major (gathered rows). B^T[n][k] k-contiguous (pre-transposed W).
// IS_G1: A = g_xr by token, B = g_w1t  -> gelu -> g_hbuf
// else : A = g_hbuf rows,   B = g_w2t  -> w*(.+b2) atomic -> out
template<int KDIM, bool IS_G1>
__global__ __launch_bounds__(256, 1) void moe_gemm(const float* __restrict__ bias,
                                                   float* __restrict__ out) {
    const int e = blockIdx.z;
    const int cnt = g_cnt[e];
    const int row0 = blockIdx.y * BM;
    if (row0 >= cnt) return;
    const int off = g_off[e];
    const int n0 = blockIdx.x * BN;

    extern __shared__ char smem[];
    const uint32_t sb = smem_u32(smem);
    const int tid  = threadIdx.x;
    const int lane = tid & 31;
    const int warp = tid >> 5;
    const int wm = warp >> 2;       // 0..1
    const int wn = warp & 3;        // 0..3
    const int g  = lane >> 2;       // 0..7
    const int tig = lane & 3;       // 0..3

    int*   tok_s  = (int*)(smem + OFF_TOK);
    float* wgt_s  = (float*)(smem + OFF_WGT);
    float* bias_s = (float*)(smem + OFF_BIAS);

    if (tid < BM) {
        int gr = row0 + tid;
        int sr = (gr < cnt) ? gr : (cnt - 1);
        tok_s[tid] = g_tok[e * NTOK + sr];
        wgt_s[tid] = g_wgt[e * NTOK + sr];
    }
    bias_s[tid] = bias[(size_t)e * (IS_G1 ? FDIM : HDIM) + n0 + tid];
    __syncthreads();

    // ---- cp.async geometry ----
    // A: 4 chunks/thread: rows (tid>>3)+i*32, 16B chunk (tid&7)
    const float* aptr[4];
    #pragma unroll
    for (int i = 0; i < 4; i++) {
        int r = (tid >> 3) + i * 32;
        if (IS_G1) {
            aptr[i] = g_xr + (size_t)tok_s[r] * HDIM + (tid & 7) * 4;
        } else {
            int gr = row0 + r;
            int sr = (gr < cnt) ? gr : (cnt - 1);
            aptr[i] = g_hbuf + (size_t)(off + sr) * FDIM + (tid & 7) * 4;
        }
    }
    // B: 8 chunks/thread: n-rows (tid>>3)+i*32, k-chunk (tid&7)
    const float* wsrc = IS_G1 ? g_w1t : g_w2t;
    const float* bptr = wsrc + (size_t)e * HDIM * FDIM
                      + (size_t)(n0 + (tid >> 3)) * KDIM + (tid & 7) * 4;
    const uint32_t dA0 = sb + OFF_A + (tid >> 3) * ROW_B + (tid & 7) * 16;
    const uint32_t dB0 = sb + OFF_B + (tid >> 3) * ROW_B + (tid & 7) * 16;

    // ---- LDSM per-lane address offsets (bytes) ----
    const uint32_t a_off = sb + OFF_A + (uint32_t)(wm * 64 + (lane & 15)) * ROW_B
                         + ((lane >> 4) & 1) * 16;
    const uint32_t b_off = sb + OFF_B
                         + (uint32_t)(wn * 64 + (lane & 7) + ((lane >> 4) & 1) * 8) * ROW_B
                         + ((lane >> 3) & 1) * 16;

    constexpr int NK = KDIM / BK;

    #define LOAD_TILE(T) do { \
        const int _s = (T) % NSTAGE; \
        const uint32_t _da = dA0 + _s * A_STAGE; \
        const uint32_t _db = dB0 + _s * B_STAGE; \
        _Pragma("unroll") \
        for (int _i = 0; _i < 4; _i++) \
            CP16(_da + _i * (32 * ROW_B), aptr[_i] + (T) * BK); \
        _Pragma("unroll") \
        for (int _i = 0; _i < 8; _i++) \
            CP16(_db + _i * (32 * ROW_B), bptr + (size_t)_i * 32 * KDIM + (T) * BK); \
        CP_COMMIT(); \
    } while (0)

    float acc[4][8][4];
    #pragma unroll
    for (int mt = 0; mt < 4; mt++)
        #pragma unroll
        for (int nt = 0; nt < 8; nt++)
            #pragma unroll
            for (int i = 0; i < 4; i++) acc[mt][nt][i] = 0.f;

    LOAD_TILE(0);
    LOAD_TILE(1);
    LOAD_TILE(2);

    for (int kt = 0; kt < NK; ++kt) {
        if (kt + 2 < NK) {
            asm volatile("cp.async.wait_group 2;" ::: "memory");
        } else if (kt + 1 < NK) {
            asm volatile("cp.async.wait_group 1;" ::: "memory");
        } else {
            asm volatile("cp.async.wait_group 0;" ::: "memory");
        }
        __syncthreads();
        if (kt + 3 < NK) LOAD_TILE(kt + 3);

        const int s = kt % NSTAGE;
        const uint32_t sA = a_off + s * A_STAGE;
        const uint32_t sB = b_off + s * B_STAGE;

        #pragma unroll
        for (int ks = 0; ks < 4; ks++) {
            uint32_t a[4][4], b[8][2];
            #pragma unroll
            for (int mt = 0; mt < 4; mt++)
                LDSM4(a[mt][0], a[mt][1], a[mt][2], a[mt][3],
                      sA + mt * (16 * ROW_B) + ks * 32);
            #pragma unroll
            for (int j = 0; j < 4; j++)
                LDSM4(b[2 * j][0], b[2 * j][1], b[2 * j + 1][0], b[2 * j + 1][1],
                      sB + j * (16 * ROW_B) + ks * 32);
            #pragma unroll
            for (int mt = 0; mt < 4; mt++)
                #pragma unroll
                for (int nt = 0; nt < 8; nt++)
                    mma_tf32(acc[mt][nt], a[mt], b[nt]);
        }
    }
    #undef LOAD_TILE
    __syncthreads();

    // ---- epilogue ----
    #pragma unroll
    for (int mt = 0; mt < 4; mt++) {
        #pragma unroll
        for (int half = 0; half < 2; half++) {
            const int rl = wm * 64 + mt * 16 + g + half * 8;
            const int gr = row0 + rl;
            if (gr < cnt) {
                if (IS_G1) {
                    float* hrow = g_hbuf + (size_t)(off + gr) * FDIM + n0 + wn * 64;
                    #pragma unroll
                    for (int nt = 0; nt < 8; nt++) {
                        int c = nt * 8 + tig * 2;
                        float b0 = bias_s[wn * 64 + c];
                        float b1v = bias_s[wn * 64 + c + 1];
                        float v0 = tf32r(gelu_exact(acc[mt][nt][half * 2 + 0] + b0));
                        float v1 = tf32r(gelu_exact(acc[mt][nt][half * 2 + 1] + b1v));
                        *(float2*)(hrow + c) = make_float2(v0, v1);
                    }
                } else {
                    const int   tok = tok_s[rl];
                    const float w   = wgt_s[rl];
                    float* orow = out + (size_t)tok * HDIM + n0 + wn * 64;
                    #pragma unroll
                    for (int nt = 0; nt < 8; nt++) {
                        int c = nt * 8 + tig * 2;
                        float v0 = w * (acc[mt][nt][half * 2 + 0] + bias_s[wn * 64 + c]);
                        float v1 = w * (acc[mt][nt][half * 2 + 1] + bias_s[wn * 64 + c + 1]);
                        atomicAdd(orow + c,     v0);
                        atomicAdd(orow + c + 1, v1);
                    }
                }
            }
        }
    }
}

// ---------------- launch -----------------------------------------------------
extern "C" void kernel_launch(void* const* d_in, const int* in_sizes, int n_in,
                              void* d_out, int out_size) {
    const float* x    = (const float*)d_in[0];
    const float* grad = (const float*)d_in[1];
    const float* Wr   = (const float*)d_in[2];
    const float* br   = (const float*)d_in[3];
    const float* W1   = (const float*)d_in[4];
    const float* b1   = (const float*)d_in[5];
    const float* W2   = (const float*)d_in[6];
    const float* b2   = (const float*)d_in[7];
    float* out = (float*)d_out;

    cudaFuncSetAttribute(moe_gemm<HDIM, true>,
                         cudaFuncAttributeMaxDynamicSharedMemorySize, SMEM_TOTAL);
    cudaFuncSetAttribute(moe_gemm<FDIM, false>,
                         cudaFuncAttributeMaxDynamicSharedMemorySize, SMEM_TOTAL);

    int nf4 = out_size / 4;
    zero_kernel<<<(nf4 + 255) / 256, 256>>>((float4*)out, nf4);

    float* xr; cudaGetSymbolAddress((void**)&xr, g_xr);
    round_kernel<<<NTOK * HDIM / 1024, 256>>>((const float4*)x, (float4*)xr);
    transpose_kernel<<<dim3(FDIM / 32, HDIM / 32, NEXP), 256>>>(W1, HDIM, FDIM, 0);
    transpose_kernel<<<dim3(HDIM / 32, FDIM / 32, NEXP), 256>>>(W2, FDIM, HDIM, 1);

    router_kernel<<<NTOK / 8, 256>>>(x, grad, Wr, br);
    prefix_kernel<<<1, 32>>>();

    moe_gemm<HDIM, true>
        <<<dim3(FDIM / BN, NTOK / BM, NEXP), 256, SMEM_TOTAL>>>(b1, nullptr);
    moe_gemm<FDIM, false>
        <<<dim3(HDIM / BN, NTOK / BM, NEXP), 256, SMEM_TOTAL>>>(b2, out);
}

// round 5
// speedup vs baseline: 1.5741x; 1.5741x over previous
#include <cuda_runtime.h>
#include <cuda_fp16.h>
#include <cstdint>

#define NTOK 8192
#define HDIM 1024
#define FDIM 4096
#define NEXP 8

#define BM 128
#define BN 256
#define BK 32          /* halves per k-tile */
#define NSTAGE 4

// SMEM rows: 32 halves (64B) padded to 80B -> conflict-free LDSM phases.
#define ROW 80
#define A_STAGE (BM * ROW)             /* 10240 */
#define B_STAGE (BN * ROW)             /* 20480 */
#define OFF_TOK  0
#define OFF_WGT  512
#define OFF_BIAS 1024
#define OFF_A    2048
#define OFF_B    (OFF_A + NSTAGE * A_STAGE)
#define SMEM_TOTAL (OFF_B + NSTAGE * B_STAGE)   /* 124928 */

// ---------------- scratch (device globals: no allocation allowed) ----------
__device__ int    g_cnt[NEXP];
__device__ int    g_off[NEXP];
__device__ int    g_tok[NEXP * NTOK];
__device__ float  g_wgt[NEXP * NTOK];
__device__ __half g_hbuf[(size_t)(2 * NTOK) * FDIM];            // 128 MB fp16
__device__ __half g_xh  [(size_t)NTOK * HDIM];                  // 16 MB  fp16 x
__device__ __half g_w1h [(size_t)NEXP * (size_t)HDIM * FDIM];   // W1^T fp16 [e][f][h]
__device__ __half g_w2h [(size_t)NEXP * (size_t)FDIM * HDIM];   // W2^T fp16 [e][h][f]

// ---------------- helpers ---------------------------------------------------
__device__ __forceinline__ uint32_t smem_u32(const void* p) {
    uint32_t a;
    asm("{ .reg .u64 t; cvta.to.shared.u64 t, %1; cvt.u32.u64 %0, t; }" : "=r"(a) : "l"(p));
    return a;
}

__device__ __forceinline__ void mma_f16(float* c, const uint32_t* a, const uint32_t* b) {
    asm("mma.sync.aligned.m16n8k16.row.col.f32.f16.f16.f32 "
        "{%0,%1,%2,%3}, {%4,%5,%6,%7}, {%8,%9}, {%0,%1,%2,%3};"
        : "+f"(c[0]), "+f"(c[1]), "+f"(c[2]), "+f"(c[3])
        : "r"(a[0]), "r"(a[1]), "r"(a[2]), "r"(a[3]),
          "r"(b[0]), "r"(b[1]));
}

#define LDSM4(r0, r1, r2, r3, addr) \
    asm volatile("ldmatrix.sync.aligned.m8n8.x4.shared.b16 {%0,%1,%2,%3}, [%4];" \
                 : "=r"(r0), "=r"(r1), "=r"(r2), "=r"(r3) : "r"(addr))

__device__ __forceinline__ float gelu_exact(float v) {
    return 0.5f * v * (1.0f + erff(v * 0.70710678118654752440f));
}

#define CP16(dst, src) \
    asm volatile("cp.async.cg.shared.global [%0], [%1], 16;" \
                 :: "r"((uint32_t)(dst)), "l"(__cvta_generic_to_global(src)))
#define CP_COMMIT() asm volatile("cp.async.commit_group;" ::: "memory")

// ---------------- kernel: zero out + counters -------------------------------
__global__ void zero_kernel(float4* out, int nf4) {
    int i = blockIdx.x * 256 + threadIdx.x;
    if (i < nf4) out[i] = make_float4(0.f, 0.f, 0.f, 0.f);
    if (i < NEXP) g_cnt[i] = 0;
}

// ---------------- kernel: x -> fp16 ------------------------------------------
__global__ void xcvt_kernel(const float4* __restrict__ src) {
    size_t i = (size_t)blockIdx.x * 256 + threadIdx.x;  // 8 halves / thread
    float4 a = src[2 * i];
    float4 b = src[2 * i + 1];
    __half2 h[4];
    h[0] = __floats2half2_rn(a.x, a.y);
    h[1] = __floats2half2_rn(a.z, a.w);
    h[2] = __floats2half2_rn(b.x, b.y);
    h[3] = __floats2half2_rn(b.z, b.w);
    *(uint4*)(g_xh + i * 8) = *(uint4*)h;
}

// ---------------- kernel: transpose weights fp32 -> fp16 ---------------------
// src[e][r][c] -> dst[e][c][r]
__global__ void transpose_h(const float* __restrict__ src, __half* __restrict__ dst,
                            int R, int C) {
    __shared__ float t[32][33];
    int e = blockIdx.z;
    int c0 = blockIdx.x * 32, r0 = blockIdx.y * 32;
    const float* s = src + (size_t)e * R * C;
    __half* d = dst + (size_t)e * R * C;
    int tx = threadIdx.x & 31, ty = threadIdx.x >> 5;   // 32 x 8
    #pragma unroll
    for (int i = 0; i < 4; i++) {
        int r = r0 + ty + i * 8;
        t[ty + i * 8][tx] = s[(size_t)r * C + c0 + tx];
    }
    __syncthreads();
    #pragma unroll
    for (int i = 0; i < 4; i++) {
        int c = c0 + ty + i * 8;
        d[(size_t)c * R + r0 + tx] = __float2half_rn(t[tx][ty + i * 8]);
    }
}

// ---------------- kernel: router (one warp per token) -----------------------
__global__ void router_kernel(const float* __restrict__ x,
                              const float* __restrict__ grad,
                              const float* __restrict__ Wr,
                              const float* __restrict__ br) {
    int n = blockIdx.x * 8 + (threadIdx.x >> 5);
    int lane = threadIdx.x & 31;
    if (n >= NTOK) return;

    float acc[NEXP];
    #pragma unroll
    for (int e = 0; e < NEXP; e++) acc[e] = 0.f;

    const float* xr = x + (size_t)n * HDIM;
    for (int h = lane; h < HDIM; h += 32) {
        float xv = xr[h];
        const float* wrow = Wr + h * NEXP;
        #pragma unroll
        for (int e = 0; e < NEXP; e++) acc[e] = fmaf(xv, wrow[e], acc[e]);
    }
    #pragma unroll
    for (int e = 0; e < NEXP; e++) {
        #pragma unroll
        for (int off = 16; off > 0; off >>= 1)
            acc[e] += __shfl_xor_sync(0xffffffffu, acc[e], off);
    }
    if (lane == 0) {
        float gv = grad[n];
        float l[NEXP];
        #pragma unroll
        for (int e = 0; e < NEXP; e++)
            l[e] = acc[e] + gv * Wr[HDIM * NEXP + e] + br[e];
        float m = l[0];
        #pragma unroll
        for (int e = 1; e < NEXP; e++) m = fmaxf(m, l[e]);
        float p[NEXP];
        float s = 0.f;
        #pragma unroll
        for (int e = 0; e < NEXP; e++) { p[e] = expf(l[e] - m); s += p[e]; }
        float inv = 1.f / s;
        int i1 = 0;
        #pragma unroll
        for (int e = 1; e < NEXP; e++) if (p[e] > p[i1]) i1 = e;
        int i2 = (i1 == 0) ? 1 : 0;
        #pragma unroll
        for (int e = 0; e < NEXP; e++) if (e != i1 && p[e] > p[i2]) i2 = e;

        int s1 = atomicAdd(&g_cnt[i1], 1);
        g_tok[i1 * NTOK + s1] = n;  g_wgt[i1 * NTOK + s1] = p[i1] * inv;
        int s2 = atomicAdd(&g_cnt[i2], 1);
        g_tok[i2 * NTOK + s2] = n;  g_wgt[i2 * NTOK + s2] = p[i2] * inv;
    }
}

__global__ void prefix_kernel() {
    if (threadIdx.x == 0) {
        int s = 0;
        #pragma unroll
        for (int e = 0; e < NEXP; e++) { g_off[e] = s; s += g_cnt[e]; }
    }
}

// ---------------- pipelined grouped GEMM (fp16 HMMA m16n8k16 + LDSM) --------
// A[BM,KDIM] k-major fp16 (gathered rows). B^T[n][k] k-contiguous fp16.
// IS_G1: A = g_xh by token, B = g_w1h  -> gelu -> g_hbuf (fp16)
// else : A = g_hbuf rows,   B = g_w2h  -> w*(.+b2) atomic -> out (fp32)
template<int KDIM, bool IS_G1>
__global__ __launch_bounds__(256, 1) void moe_gemm(const float* __restrict__ bias,
                                                   float* __restrict__ out) {
    const int e = blockIdx.z;
    const int cnt = g_cnt[e];
    const int row0 = blockIdx.y * BM;
    if (row0 >= cnt) return;
    const int off = g_off[e];
    const int n0 = blockIdx.x * BN;

    extern __shared__ char smem[];
    const uint32_t sb = smem_u32(smem);
    const int tid  = threadIdx.x;
    const int lane = tid & 31;
    const int warp = tid >> 5;
    const int wm = warp >> 2;       // 0..1
    const int wn = warp & 3;        // 0..3
    const int g  = lane >> 2;       // 0..7
    const int tig = lane & 3;       // 0..3

    int*   tok_s  = (int*)(smem + OFF_TOK);
    float* wgt_s  = (float*)(smem + OFF_WGT);
    float* bias_s = (float*)(smem + OFF_BIAS);

    if (tid < BM) {
        int gr = row0 + tid;
        int sr = (gr < cnt) ? gr : (cnt - 1);
        tok_s[tid] = g_tok[e * NTOK + sr];
        wgt_s[tid] = g_wgt[e * NTOK + sr];
    }
    bias_s[tid] = bias[(size_t)e * (IS_G1 ? FDIM : HDIM) + n0 + tid];
    __syncthreads();

    // ---- cp.async geometry (16B = 8 halves per chunk) ----
    // A: 2 chunks/thread: rows (tid>>2)+i*64, chunk (tid&3)
    const __half* aptr[2];
    #pragma unroll
    for (int i = 0; i < 2; i++) {
        int r = (tid >> 2) + i * 64;
        if (IS_G1) {
            aptr[i] = g_xh + (size_t)tok_s[r] * HDIM + (tid & 3) * 8;
        } else {
            int gr = row0 + r;
            int sr = (gr < cnt) ? gr : (cnt - 1);
            aptr[i] = g_hbuf + (size_t)(off + sr) * FDIM + (tid & 3) * 8;
        }
    }
    // B: 4 chunks/thread: n-rows (tid>>2)+i*64
    const __half* wsrc = IS_G1 ? g_w1h : g_w2h;
    const __half* bptr = wsrc + (size_t)e * HDIM * FDIM
                       + (size_t)(n0 + (tid >> 2)) * KDIM + (tid & 3) * 8;
    const uint32_t dA0 = sb + OFF_A + (tid >> 2) * ROW + (tid & 3) * 16;
    const uint32_t dB0 = sb + OFF_B + (tid >> 2) * ROW + (tid & 3) * 16;

    // ---- LDSM per-lane base addresses ----
    const uint32_t a_off = sb + OFF_A + (uint32_t)(wm * 64 + (lane & 15)) * ROW
                         + ((lane >> 4) & 1) * 16;
    const uint32_t b_off = sb + OFF_B
                         + (uint32_t)(wn * 64 + (lane & 7) + ((lane >> 4) & 1) * 8) * ROW
                         + ((lane >> 3) & 1) * 16;

    constexpr int NK = KDIM / BK;

    #define LOAD_TILE(T) do { \
        const int _s = (T) % NSTAGE; \
        const uint32_t _da = dA0 + _s * A_STAGE; \
        const uint32_t _db = dB0 + _s * B_STAGE; \
        _Pragma("unroll") \
        for (int _i = 0; _i < 2; _i++) \
            CP16(_da + _i * (64 * ROW), aptr[_i] + (T) * BK); \
        _Pragma("unroll") \
        for (int _i = 0; _i < 4; _i++) \
            CP16(_db + _i * (64 * ROW), bptr + (size_t)_i * 64 * KDIM + (T) * BK); \
        CP_COMMIT(); \
    } while (0)

    float acc[4][8][4];
    #pragma unroll
    for (int mt = 0; mt < 4; mt++)
        #pragma unroll
        for (int nt = 0; nt < 8; nt++)
            #pragma unroll
            for (int i = 0; i < 4; i++) acc[mt][nt][i] = 0.f;

    LOAD_TILE(0);
    LOAD_TILE(1);
    LOAD_TILE(2);

    for (int kt = 0; kt < NK; ++kt) {
        if (kt + 3 <= NK) {
            asm volatile("cp.async.wait_group 2;" ::: "memory");
        } else if (kt + 2 == NK) {
            asm volatile("cp.async.wait_group 1;" ::: "memory");
        } else {
            asm volatile("cp.async.wait_group 0;" ::: "memory");
        }
        __syncthreads();
        if (kt + 3 < NK) LOAD_TILE(kt + 3);

        const int s = kt % NSTAGE;
        const uint32_t sA = a_off + s * A_STAGE;
        const uint32_t sB = b_off + s * B_STAGE;

        #pragma unroll
        for (int ks = 0; ks < 2; ks++) {           // two k16 steps per 32-half tile
            uint32_t a[4][4], b[8][2];
            #pragma unroll
            for (int mt = 0; mt < 4; mt++)
                LDSM4(a[mt][0], a[mt][1], a[mt][2], a[mt][3],
                      sA + mt * (16 * ROW) + ks * 32);
            #pragma unroll
            for (int j = 0; j < 4; j++)
                LDSM4(b[2 * j][0], b[2 * j][1], b[2 * j + 1][0], b[2 * j + 1][1],
                      sB + j * (16 * ROW) + ks * 32);
            #pragma unroll
            for (int mt = 0; mt < 4; mt++)
                #pragma unroll
                for (int nt = 0; nt < 8; nt++)
                    mma_f16(acc[mt][nt], a[mt], b[nt]);
        }
    }
    #undef LOAD_TILE
    __syncthreads();

    // ---- epilogue ----
    #pragma unroll
    for (int mt = 0; mt < 4; mt++) {
        #pragma unroll
        for (int half = 0; half < 2; half++) {
            const int rl = wm * 64 + mt * 16 + g + half * 8;
            const int gr = row0 + rl;
            if (gr < cnt) {
                if (IS_G1) {
                    __half* hrow = g_hbuf + (size_t)(off + gr) * FDIM + n0 + wn * 64;
                    #pragma unroll
                    for (int nt = 0; nt < 8; nt++) {
                        int c = nt * 8 + tig * 2;
                        float v0 = gelu_exact(acc[mt][nt][half * 2 + 0] + bias_s[wn * 64 + c]);
                        float v1 = gelu_exact(acc[mt][nt][half * 2 + 1] + bias_s[wn * 64 + c + 1]);
                        *(__half2*)(hrow + c) = __floats2half2_rn(v0, v1);
                    }
                } else {
                    const int   tok = tok_s[rl];
                    const float w   = wgt_s[rl];
                    float* orow = out + (size_t)tok * HDIM + n0 + wn * 64;
                    #pragma unroll
                    for (int nt = 0; nt < 8; nt++) {
                        int c = nt * 8 + tig * 2;
                        float v0 = w * (acc[mt][nt][half * 2 + 0] + bias_s[wn * 64 + c]);
                        float v1 = w * (acc[mt][nt][half * 2 + 1] + bias_s[wn * 64 + c + 1]);
                        atomicAdd(orow + c,     v0);
                        atomicAdd(orow + c + 1, v1);
                    }
                }
            }
        }
    }
}

// ---------------- launch -----------------------------------------------------
extern "C" void kernel_launch(void* const* d_in, const int* in_sizes, int n_in,
                              void* d_out, int out_size) {
    const float* x    = (const float*)d_in[0];
    const float* grad = (const float*)d_in[1];
    const float* Wr   = (const float*)d_in[2];
    const float* br   = (const float*)d_in[3];
    const float* W1   = (const float*)d_in[4];
    const float* b1   = (const float*)d_in[5];
    const float* W2   = (const float*)d_in[6];
    const float* b2   = (const float*)d_in[7];
    float* out = (float*)d_out;

    cudaFuncSetAttribute(moe_gemm<HDIM, true>,
                         cudaFuncAttributeMaxDynamicSharedMemorySize, SMEM_TOTAL);
    cudaFuncSetAttribute(moe_gemm<FDIM, false>,
                         cudaFuncAttributeMaxDynamicSharedMemorySize, SMEM_TOTAL);

    int nf4 = out_size / 4;
    zero_kernel<<<(nf4 + 255) / 256, 256>>>((float4*)out, nf4);

    __half* w1h; cudaGetSymbolAddress((void**)&w1h, g_w1h);
    __half* w2h; cudaGetSymbolAddress((void**)&w2h, g_w2h);
    xcvt_kernel<<<NTOK * HDIM / (256 * 8), 256>>>((const float4*)x);
    transpose_h<<<dim3(FDIM / 32, HDIM / 32, NEXP), 256>>>(W1, w1h, HDIM, FDIM);
    transpose_h<<<dim3(HDIM / 32, FDIM / 32, NEXP), 256>>>(W2, w2h, FDIM, HDIM);

    router_kernel<<<NTOK / 8, 256>>>(x, grad, Wr, br);
    prefix_kernel<<<1, 32>>>();

    moe_gemm<HDIM, true>
        <<<dim3(FDIM / BN, NTOK / BM, NEXP), 256, SMEM_TOTAL>>>(b1, nullptr);
    moe_gemm<FDIM, false>
        <<<dim3(HDIM / BN, NTOK / BM, NEXP), 256, SMEM_TOTAL>>>(b2, out);
}

// round 6
// speedup vs baseline: 1.6473x; 1.0465x over previous
#include <cuda_runtime.h>
#include <cuda_fp16.h>
#include <cstdint>

#define NTOK 8192
#define HDIM 1024
#define FDIM 4096
#define NEXP 8

#define BM 64
#define BN 256
#define BK 32          /* halves per k-tile */
#define NSTAGE 4

// SMEM rows: 32 halves (64B) padded to 80B -> conflict-free LDSM phases.
#define ROW 80
#define A_STAGE (BM * ROW)             /* 5120 */
#define B_STAGE (BN * ROW)             /* 20480 */
#define OFF_TOK  0
#define OFF_WGT  256
#define OFF_BIAS 1024
#define OFF_A    2048
#define OFF_B    (OFF_A + NSTAGE * A_STAGE)
#define SMEM_TOTAL (OFF_B + NSTAGE * B_STAGE)   /* 104448 */

// ---------------- scratch (device globals: no allocation allowed) ----------
__device__ int    g_cnt[NEXP];
__device__ int    g_off[NEXP];
__device__ int    g_tok[NEXP * NTOK];
__device__ float  g_wgt[NEXP * NTOK];
__device__ __half g_hbuf[(size_t)(2 * NTOK) * FDIM];            // 128 MB fp16
__device__ __half g_xh  [(size_t)NTOK * HDIM];                  // 16 MB  fp16 x
__device__ __half g_w1h [(size_t)NEXP * (size_t)HDIM * FDIM];   // W1^T fp16 [e][f][h]
__device__ __half g_w2h [(size_t)NEXP * (size_t)FDIM * HDIM];   // W2^T fp16 [e][h][f]

// ---------------- helpers ---------------------------------------------------
__device__ __forceinline__ uint32_t smem_u32(const void* p) {
    uint32_t a;
    asm("{ .reg .u64 t; cvta.to.shared.u64 t, %1; cvt.u32.u64 %0, t; }" : "=r"(a) : "l"(p));
    return a;
}

__device__ __forceinline__ void mma_f16(float* c, const uint32_t* a, const uint32_t* b) {
    asm("mma.sync.aligned.m16n8k16.row.col.f32.f16.f16.f32 "
        "{%0,%1,%2,%3}, {%4,%5,%6,%7}, {%8,%9}, {%0,%1,%2,%3};"
        : "+f"(c[0]), "+f"(c[1]), "+f"(c[2]), "+f"(c[3])
        : "r"(a[0]), "r"(a[1]), "r"(a[2]), "r"(a[3]),
          "r"(b[0]), "r"(b[1]));
}

#define LDSM4(r0, r1, r2, r3, addr) \
    asm volatile("ldmatrix.sync.aligned.m8n8.x4.shared.b16 {%0,%1,%2,%3}, [%4];" \
                 : "=r"(r0), "=r"(r1), "=r"(r2), "=r"(r3) : "r"(addr))

__device__ __forceinline__ float gelu_exact(float v) {
    return 0.5f * v * (1.0f + erff(v * 0.70710678118654752440f));
}

#define CP16(dst, src) \
    asm volatile("cp.async.cg.shared.global [%0], [%1], 16;" \
                 :: "r"((uint32_t)(dst)), "l"(__cvta_generic_to_global(src)))
#define CP_COMMIT() asm volatile("cp.async.commit_group;" ::: "memory")

// ---------------- kernel: zero out + counters -------------------------------
__global__ void zero_kernel(float4* out, int nf4) {
    int i = blockIdx.x * 256 + threadIdx.x;
    if (i < nf4) out[i] = make_float4(0.f, 0.f, 0.f, 0.f);
    if (i < NEXP) g_cnt[i] = 0;
}

// ---------------- kernel: x -> fp16 ------------------------------------------
__global__ void xcvt_kernel(const float4* __restrict__ src) {
    size_t i = (size_t)blockIdx.x * 256 + threadIdx.x;  // 8 halves / thread
    float4 a = src[2 * i];
    float4 b = src[2 * i + 1];
    __half2 h[4];
    h[0] = __floats2half2_rn(a.x, a.y);
    h[1] = __floats2half2_rn(a.z, a.w);
    h[2] = __floats2half2_rn(b.x, b.y);
    h[3] = __floats2half2_rn(b.z, b.w);
    *(uint4*)(g_xh + i * 8) = *(uint4*)h;
}

// ---------------- kernel: transpose weights fp32 -> fp16 ---------------------
// src[e][r][c] -> dst[e][c][r]
__global__ void transpose_h(const float* __restrict__ src, __half* __restrict__ dst,
                            int R, int C) {
    __shared__ float t[32][33];
    int e = blockIdx.z;
    int c0 = blockIdx.x * 32, r0 = blockIdx.y * 32;
    const float* s = src + (size_t)e * R * C;
    __half* d = dst + (size_t)e * R * C;
    int tx = threadIdx.x & 31, ty = threadIdx.x >> 5;   // 32 x 8
    #pragma unroll
    for (int i = 0; i < 4; i++) {
        int r = r0 + ty + i * 8;
        t[ty + i * 8][tx] = s[(size_t)r * C + c0 + tx];
    }
    __syncthreads();
    #pragma unroll
    for (int i = 0; i < 4; i++) {
        int c = c0 + ty + i * 8;
        d[(size_t)c * R + r0 + tx] = __float2half_rn(t[tx][ty + i * 8]);
    }
}

// ---------------- kernel: router (one warp per token) -----------------------
__global__ void router_kernel(const float* __restrict__ x,
                              const float* __restrict__ grad,
                              const float* __restrict__ Wr,
                              const float* __restrict__ br) {
    int n = blockIdx.x * 8 + (threadIdx.x >> 5);
    int lane = threadIdx.x & 31;
    if (n >= NTOK) return;

    float acc[NEXP];
    #pragma unroll
    for (int e = 0; e < NEXP; e++) acc[e] = 0.f;

    const float* xr = x + (size_t)n * HDIM;
    for (int h = lane; h < HDIM; h += 32) {
        float xv = xr[h];
        const float* wrow = Wr + h * NEXP;
        #pragma unroll
        for (int e = 0; e < NEXP; e++) acc[e] = fmaf(xv, wrow[e], acc[e]);
    }
    #pragma unroll
    for (int e = 0; e < NEXP; e++) {
        #pragma unroll
        for (int off = 16; off > 0; off >>= 1)
            acc[e] += __shfl_xor_sync(0xffffffffu, acc[e], off);
    }
    if (lane == 0) {
        float gv = grad[n];
        float l[NEXP];
        #pragma unroll
        for (int e = 0; e < NEXP; e++)
            l[e] = acc[e] + gv * Wr[HDIM * NEXP + e] + br[e];
        float m = l[0];
        #pragma unroll
        for (int e = 1; e < NEXP; e++) m = fmaxf(m, l[e]);
        float p[NEXP];
        float s = 0.f;
        #pragma unroll
        for (int e = 0; e < NEXP; e++) { p[e] = expf(l[e] - m); s += p[e]; }
        float inv = 1.f / s;
        int i1 = 0;
        #pragma unroll
        for (int e = 1; e < NEXP; e++) if (p[e] > p[i1]) i1 = e;
        int i2 = (i1 == 0) ? 1 : 0;
        #pragma unroll
        for (int e = 0; e < NEXP; e++) if (e != i1 && p[e] > p[i2]) i2 = e;

        int s1 = atomicAdd(&g_cnt[i1], 1);
        g_tok[i1 * NTOK + s1] = n;  g_wgt[i1 * NTOK + s1] = p[i1] * inv;
        int s2 = atomicAdd(&g_cnt[i2], 1);
        g_tok[i2 * NTOK + s2] = n;  g_wgt[i2 * NTOK + s2] = p[i2] * inv;
    }
}

__global__ void prefix_kernel() {
    if (threadIdx.x == 0) {
        int s = 0;
        #pragma unroll
        for (int e = 0; e < NEXP; e++) { g_off[e] = s; s += g_cnt[e]; }
    }
}

// ---------------- pipelined grouped GEMM (fp16 HMMA, 64x256 tile, occ 2) -----
// A[BM,KDIM] k-major fp16 (gathered rows). B^T[n][k] k-contiguous fp16.
// IS_G1: A = g_xh by token, B = g_w1h  -> gelu -> g_hbuf (fp16)
// else : A = g_hbuf rows,   B = g_w2h  -> w*(.+b2) atomic -> out (fp32)
template<int KDIM, bool IS_G1>
__global__ __launch_bounds__(256, 2) void moe_gemm(const float* __restrict__ bias,
                                                   float* __restrict__ out) {
    const int e = blockIdx.z;
    const int cnt = g_cnt[e];
    const int row0 = blockIdx.y * BM;
    if (row0 >= cnt) return;
    const int off = g_off[e];
    const int n0 = blockIdx.x * BN;

    extern __shared__ char smem[];
    const uint32_t sb = smem_u32(smem);
    const int tid  = threadIdx.x;
    const int lane = tid & 31;
    const int warp = tid >> 5;
    const int wm = warp >> 2;       // 0..1 (32 rows each)
    const int wn = warp & 3;        // 0..3 (64 cols each)
    const int g  = lane >> 2;       // 0..7
    const int tig = lane & 3;       // 0..3

    int*   tok_s  = (int*)(smem + OFF_TOK);
    float* wgt_s  = (float*)(smem + OFF_WGT);
    float* bias_s = (float*)(smem + OFF_BIAS);

    if (tid < BM) {
        int gr = row0 + tid;
        int sr = (gr < cnt) ? gr : (cnt - 1);
        tok_s[tid] = g_tok[e * NTOK + sr];
        wgt_s[tid] = g_wgt[e * NTOK + sr];
    }
    bias_s[tid] = bias[(size_t)e * (IS_G1 ? FDIM : HDIM) + n0 + tid];
    __syncthreads();

    // ---- cp.async geometry (16B = 8 halves per chunk) ----
    // A: 1 chunk/thread: row tid>>2 (0..63), chunk tid&3
    const __half* aptr;
    {
        int r = tid >> 2;
        if (IS_G1) {
            aptr = g_xh + (size_t)tok_s[r] * HDIM + (tid & 3) * 8;
        } else {
            int gr = row0 + r;
            int sr = (gr < cnt) ? gr : (cnt - 1);
            aptr = g_hbuf + (size_t)(off + sr) * FDIM + (tid & 3) * 8;
        }
    }
    // B: 4 chunks/thread: n-rows (tid>>2)+i*64
    const __half* wsrc = IS_G1 ? g_w1h : g_w2h;
    const __half* bptr = wsrc + (size_t)e * HDIM * FDIM
                       + (size_t)(n0 + (tid >> 2)) * KDIM + (tid & 3) * 8;
    const uint32_t dA0 = sb + OFF_A + (tid >> 2) * ROW + (tid & 3) * 16;
    const uint32_t dB0 = sb + OFF_B + (tid >> 2) * ROW + (tid & 3) * 16;

    // ---- LDSM per-lane base addresses ----
    const uint32_t a_off = sb + OFF_A + (uint32_t)(wm * 32 + (lane & 15)) * ROW
                         + ((lane >> 4) & 1) * 16;
    const uint32_t b_off = sb + OFF_B
                         + (uint32_t)(wn * 64 + (lane & 7) + ((lane >> 4) & 1) * 8) * ROW
                         + ((lane >> 3) & 1) * 16;

    constexpr int NK = KDIM / BK;

    #define LOAD_TILE(T) do { \
        const int _s = (T) % NSTAGE; \
        CP16(dA0 + _s * A_STAGE, aptr + (T) * BK); \
        const uint32_t _db = dB0 + _s * B_STAGE; \
        _Pragma("unroll") \
        for (int _i = 0; _i < 4; _i++) \
            CP16(_db + _i * (64 * ROW), bptr + (size_t)_i * 64 * KDIM + (T) * BK); \
        CP_COMMIT(); \
    } while (0)

    float acc[2][8][4];
    #pragma unroll
    for (int mt = 0; mt < 2; mt++)
        #pragma unroll
        for (int nt = 0; nt < 8; nt++)
            #pragma unroll
            for (int i = 0; i < 4; i++) acc[mt][nt][i] = 0.f;

    LOAD_TILE(0);
    LOAD_TILE(1);
    LOAD_TILE(2);

    for (int kt = 0; kt < NK; ++kt) {
        if (kt + 3 <= NK) {
            asm volatile("cp.async.wait_group 2;" ::: "memory");
        } else if (kt + 2 == NK) {
            asm volatile("cp.async.wait_group 1;" ::: "memory");
        } else {
            asm volatile("cp.async.wait_group 0;" ::: "memory");
        }
        __syncthreads();
        if (kt + 3 < NK) LOAD_TILE(kt + 3);

        const int s = kt % NSTAGE;
        const uint32_t sA = a_off + s * A_STAGE;
        const uint32_t sB = b_off + s * B_STAGE;

        #pragma unroll
        for (int ks = 0; ks < 2; ks++) {           // two k16 steps per 32-half tile
            uint32_t a[2][4], b[8][2];
            #pragma unroll
            for (int mt = 0; mt < 2; mt++)
                LDSM4(a[mt][0], a[mt][1], a[mt][2], a[mt][3],
                      sA + mt * (16 * ROW) + ks * 32);
            #pragma unroll
            for (int j = 0; j < 4; j++)
                LDSM4(b[2 * j][0], b[2 * j][1], b[2 * j + 1][0], b[2 * j + 1][1],
                      sB + j * (16 * ROW) + ks * 32);
            #pragma unroll
            for (int mt = 0; mt < 2; mt++)
                #pragma unroll
                for (int nt = 0; nt < 8; nt++)
                    mma_f16(acc[mt][nt], a[mt], b[nt]);
        }
    }
    #undef LOAD_TILE
    __syncthreads();

    // ---- epilogue ----
    #pragma unroll
    for (int mt = 0; mt < 2; mt++) {
        #pragma unroll
        for (int half = 0; half < 2; half++) {
            const int rl = wm * 32 + mt * 16 + g + half * 8;
            const int gr = row0 + rl;
            if (gr < cnt) {
                if (IS_G1) {
                    __half* hrow = g_hbuf + (size_t)(off + gr) * FDIM + n0 + wn * 64;
                    #pragma unroll
                    for (int nt = 0; nt < 8; nt++) {
                        int c = nt * 8 + tig * 2;
                        float v0 = gelu_exact(acc[mt][nt][half * 2 + 0] + bias_s[wn * 64 + c]);
                        float v1 = gelu_exact(acc[mt][nt][half * 2 + 1] + bias_s[wn * 64 + c + 1]);
                        *(__half2*)(hrow + c) = __floats2half2_rn(v0, v1);
                    }
                } else {
                    const int   tok = tok_s[rl];
                    const float w   = wgt_s[rl];
                    float* orow = out + (size_t)tok * HDIM + n0 + wn * 64;
                    #pragma unroll
                    for (int nt = 0; nt < 8; nt++) {
                        int c = nt * 8 + tig * 2;
                        float v0 = w * (acc[mt][nt][half * 2 + 0] + bias_s[wn * 64 + c]);
                        float v1 = w * (acc[mt][nt][half * 2 + 1] + bias_s[wn * 64 + c + 1]);
                        atomicAdd(orow + c,     v0);
                        atomicAdd(orow + c + 1, v1);
                    }
                }
            }
        }
    }
}

// ---------------- launch -----------------------------------------------------
extern "C" void kernel_launch(void* const* d_in, const int* in_sizes, int n_in,
                              void* d_out, int out_size) {
    const float* x    = (const float*)d_in[0];
    const float* grad = (const float*)d_in[1];
    const float* Wr   = (const float*)d_in[2];
    const float* br   = (const float*)d_in[3];
    const float* W1   = (const float*)d_in[4];
    const float* b1   = (const float*)d_in[5];
    const float* W2   = (const float*)d_in[6];
    const float* b2   = (const float*)d_in[7];
    float* out = (float*)d_out;

    cudaFuncSetAttribute(moe_gemm<HDIM, true>,
                         cudaFuncAttributeMaxDynamicSharedMemorySize, SMEM_TOTAL);
    cudaFuncSetAttribute(moe_gemm<FDIM, false>,
                         cudaFuncAttributeMaxDynamicSharedMemorySize, SMEM_TOTAL);

    int nf4 = out_size / 4;
    zero_kernel<<<(nf4 + 255) / 256, 256>>>((float4*)out, nf4);

    __half* w1h; cudaGetSymbolAddress((void**)&w1h, g_w1h);
    __half* w2h; cudaGetSymbolAddress((void**)&w2h, g_w2h);
    xcvt_kernel<<<NTOK * HDIM / (256 * 8), 256>>>((const float4*)x);
    transpose_h<<<dim3(FDIM / 32, HDIM / 32, NEXP), 256>>>(W1, w1h, HDIM, FDIM);
    transpose_h<<<dim3(HDIM / 32, FDIM / 32, NEXP), 256>>>(W2, w2h, FDIM, HDIM);

    router_kernel<<<NTOK / 8, 256>>>(x, grad, Wr, br);
    prefix_kernel<<<1, 32>>>();

    moe_gemm<HDIM, true>
        <<<dim3(FDIM / BN, NTOK / BM, NEXP), 256, SMEM_TOTAL>>>(b1, nullptr);
    moe_gemm<FDIM, false>
        <<<dim3(HDIM / BN, NTOK / BM, NEXP), 256, SMEM_TOTAL>>>(b2, out);
}

// round 7
// speedup vs baseline: 1.6479x; 1.0004x over previous
#include <cuda_runtime.h>
#include <cuda_fp16.h>
#include <cstdint>

#define NTOK 8192
#define HDIM 1024
#define FDIM 4096
#define NEXP 8

#define BM 64
#define BK 32          /* halves per k-tile */
#define NSTAGE 4
#define ROW 80         /* bytes per 32-half SMEM row (64B + 16B pad) */

#define OFF_TOK  0
#define OFF_WGT  256
#define OFF_BIAS 1024
#define OFF_A    2048
#define A_ST (BM * ROW)                /* 5120 */

// ---------------- scratch (device globals: no allocation allowed) ----------
__device__ int    g_cnt[NEXP];
__device__ int    g_off[NEXP];
__device__ int    g_tok[NEXP * NTOK];
__device__ float  g_wgt[NEXP * NTOK];
__device__ __half g_hbuf[(size_t)(2 * NTOK) * FDIM];            // 128 MB fp16
__device__ __half g_xh  [(size_t)NTOK * HDIM];                  // 16 MB  fp16 x
__device__ __half g_w1h [(size_t)NEXP * (size_t)HDIM * FDIM];   // W1^T fp16 [e][f][h]
__device__ __half g_w2h [(size_t)NEXP * (size_t)FDIM * HDIM];   // W2^T fp16 [e][h][f]

// ---------------- helpers ---------------------------------------------------
__device__ __forceinline__ uint32_t smem_u32(const void* p) {
    uint32_t a;
    asm("{ .reg .u64 t; cvta.to.shared.u64 t, %1; cvt.u32.u64 %0, t; }" : "=r"(a) : "l"(p));
    return a;
}

__device__ __forceinline__ void mma_f16(float* c, const uint32_t* a, const uint32_t* b) {
    asm("mma.sync.aligned.m16n8k16.row.col.f32.f16.f16.f32 "
        "{%0,%1,%2,%3}, {%4,%5,%6,%7}, {%8,%9}, {%0,%1,%2,%3};"
        : "+f"(c[0]), "+f"(c[1]), "+f"(c[2]), "+f"(c[3])
        : "r"(a[0]), "r"(a[1]), "r"(a[2]), "r"(a[3]),
          "r"(b[0]), "r"(b[1]));
}

#define LDSM4(r0, r1, r2, r3, addr) \
    asm volatile("ldmatrix.sync.aligned.m8n8.x4.shared.b16 {%0,%1,%2,%3}, [%4];" \
                 : "=r"(r0), "=r"(r1), "=r"(r2), "=r"(r3) : "r"(addr))

__device__ __forceinline__ float gelu_exact(float v) {
    return 0.5f * v * (1.0f + erff(v * 0.70710678118654752440f));
}

#define CP16(dst, src) \
    asm volatile("cp.async.cg.shared.global [%0], [%1], 16;" \
                 :: "r"((uint32_t)(dst)), "l"(__cvta_generic_to_global(src)))
#define CP_COMMIT() asm volatile("cp.async.commit_group;" ::: "memory")

// ---------------- kernel: zero expert counters -------------------------------
__global__ void zcnt_kernel() {
    if (threadIdx.x < NEXP) g_cnt[threadIdx.x] = 0;
}

// ---------------- fused prep kernel ------------------------------------------
// blockIdx ranges: [0,1024) router | [1024,33792) W1^T | [33792,66560) W2^T |
//                  [66560,70656) x->fp16 | [70656,70656+nzero) zero out
#define PREP_RTR 1024
#define PREP_T1  (PREP_RTR + 32768)
#define PREP_T2  (PREP_T1 + 32768)
#define PREP_XC  (PREP_T2 + 4096)

__device__ __forceinline__ void do_transpose(const float* __restrict__ src,
                                             __half* __restrict__ dst,
                                             int R, int C, int t,
                                             float (*tb)[33]) {
    const int nCx = C / 32;
    const int e  = t / (nCx * (R / 32));
    const int rm = t % (nCx * (R / 32));
    const int c0 = (rm % nCx) * 32;
    const int r0 = (rm / nCx) * 32;
    const float* s = src + (size_t)e * R * C;
    __half* d = dst + (size_t)e * R * C;
    int tx = threadIdx.x & 31, ty = threadIdx.x >> 5;
    #pragma unroll
    for (int i = 0; i < 4; i++)
        tb[ty + i * 8][tx] = s[(size_t)(r0 + ty + i * 8) * C + c0 + tx];
    __syncthreads();
    #pragma unroll
    for (int i = 0; i < 4; i++)
        d[(size_t)(c0 + ty + i * 8) * R + r0 + tx] = __float2half_rn(tb[tx][ty + i * 8]);
}

__global__ void prep_kernel(const float* __restrict__ x,
                            const float* __restrict__ grad,
                            const float* __restrict__ Wr,
                            const float* __restrict__ br,
                            const float* __restrict__ W1,
                            const float* __restrict__ W2,
                            float4* __restrict__ out, int nf4) {
    __shared__ float tb[32][33];
    const int bid = blockIdx.x;

    if (bid < PREP_RTR) {
        // ---- router: one warp per token ----
        int n = bid * 8 + (threadIdx.x >> 5);
        int lane = threadIdx.x & 31;
        float acc[NEXP];
        #pragma unroll
        for (int e = 0; e < NEXP; e++) acc[e] = 0.f;
        const float* xr = x + (size_t)n * HDIM;
        for (int h = lane; h < HDIM; h += 32) {
            float xv = xr[h];
            const float* wrow = Wr + h * NEXP;
            #pragma unroll
            for (int e = 0; e < NEXP; e++) acc[e] = fmaf(xv, wrow[e], acc[e]);
        }
        #pragma unroll
        for (int e = 0; e < NEXP; e++) {
            #pragma unroll
            for (int off = 16; off > 0; off >>= 1)
                acc[e] += __shfl_xor_sync(0xffffffffu, acc[e], off);
        }
        if (lane == 0) {
            float gv = grad[n];
            float l[NEXP];
            #pragma unroll
            for (int e = 0; e < NEXP; e++)
                l[e] = acc[e] + gv * Wr[HDIM * NEXP + e] + br[e];
            float m = l[0];
            #pragma unroll
            for (int e = 1; e < NEXP; e++) m = fmaxf(m, l[e]);
            float p[NEXP];
            float s = 0.f;
            #pragma unroll
            for (int e = 0; e < NEXP; e++) { p[e] = expf(l[e] - m); s += p[e]; }
            float inv = 1.f / s;
            int i1 = 0;
            #pragma unroll
            for (int e = 1; e < NEXP; e++) if (p[e] > p[i1]) i1 = e;
            int i2 = (i1 == 0) ? 1 : 0;
            #pragma unroll
            for (int e = 0; e < NEXP; e++) if (e != i1 && p[e] > p[i2]) i2 = e;
            int s1 = atomicAdd(&g_cnt[i1], 1);
            g_tok[i1 * NTOK + s1] = n;  g_wgt[i1 * NTOK + s1] = p[i1] * inv;
            int s2 = atomicAdd(&g_cnt[i2], 1);
            g_tok[i2 * NTOK + s2] = n;  g_wgt[i2 * NTOK + s2] = p[i2] * inv;
        }
    } else if (bid < PREP_T1) {
        do_transpose(W1, g_w1h, HDIM, FDIM, bid - PREP_RTR, tb);
    } else if (bid < PREP_T2) {
        do_transpose(W2, g_w2h, FDIM, HDIM, bid - PREP_T1, tb);
    } else if (bid < PREP_XC) {
        size_t i = (size_t)(bid - PREP_T2) * 256 + threadIdx.x;  // 8 halves / thread
        const float4* x4 = (const float4*)x;
        float4 a = x4[2 * i];
        float4 b = x4[2 * i + 1];
        __half2 h[4];
        h[0] = __floats2half2_rn(a.x, a.y);
        h[1] = __floats2half2_rn(a.z, a.w);
        h[2] = __floats2half2_rn(b.x, b.y);
        h[3] = __floats2half2_rn(b.z, b.w);
        *(uint4*)(g_xh + i * 8) = *(uint4*)h;
    } else {
        int i = (bid - PREP_XC) * 256 + threadIdx.x;
        if (i < nf4) out[i] = make_float4(0.f, 0.f, 0.f, 0.f);
    }
}

__global__ void prefix_kernel() {
    if (threadIdx.x == 0) {
        int s = 0;
        #pragma unroll
        for (int e = 0; e < NEXP; e++) { g_off[e] = s; s += g_cnt[e]; }
    }
}

// ---------------- pipelined grouped GEMM (fp16 HMMA, BMx BN_ tile) ----------
// A[BM,KDIM] k-major fp16 (gathered rows). B^T[n][k] k-contiguous fp16.
// IS_G1: A = g_xh by token, B = g_w1h  -> gelu -> g_hbuf (fp16)
// else : A = g_hbuf rows,   B = g_w2h  -> w*(.+b2) atomic -> out (fp32)
template<int KDIM, int BN_, bool IS_G1>
__global__ __launch_bounds__(256, 2) void moe_gemm(const float* __restrict__ bias,
                                                   float* __restrict__ out) {
    constexpr int B_ST = BN_ * ROW;
    constexpr int OFF_B = OFF_A + NSTAGE * A_ST;
    constexpr int WN = BN_ / 4;        /* n-cols per warp */
    constexpr int NT = BN_ / 32;       /* n8-frag pairs per warp */
    constexpr int NBC = BN_ / 64;      /* B cp.async chunks per thread */

    const int e = blockIdx.z;
    const int cnt = g_cnt[e];
    const int row0 = blockIdx.y * BM;
    if (row0 >= cnt) return;
    const int off = g_off[e];
    const int n0 = blockIdx.x * BN_;

    extern __shared__ char smem[];
    const uint32_t sb = smem_u32(smem);
    const int tid  = threadIdx.x;
    const int lane = tid & 31;
    const int warp = tid >> 5;
    const int wm = warp >> 2;       // 0..1 (32 rows each)
    const int wn = warp & 3;        // 0..3 (WN cols each)
    const int g  = lane >> 2;       // 0..7
    const int tig = lane & 3;       // 0..3

    int*   tok_s  = (int*)(smem + OFF_TOK);
    float* wgt_s  = (float*)(smem + OFF_WGT);
    float* bias_s = (float*)(smem + OFF_BIAS);

    if (tid < BM) {
        int gr = row0 + tid;
        int sr = (gr < cnt) ? gr : (cnt - 1);
        tok_s[tid] = g_tok[e * NTOK + sr];
        wgt_s[tid] = g_wgt[e * NTOK + sr];
    }
    if (tid < BN_)
        bias_s[tid] = bias[(size_t)e * (IS_G1 ? FDIM : HDIM) + n0 + tid];
    __syncthreads();

    // ---- cp.async geometry (16B = 8 halves per chunk) ----
    const __half* aptr;
    {
        int r = tid >> 2;
        if (IS_G1) {
            aptr = g_xh + (size_t)tok_s[r] * HDIM + (tid & 3) * 8;
        } else {
            int gr = row0 + r;
            int sr = (gr < cnt) ? gr : (cnt - 1);
            aptr = g_hbuf + (size_t)(off + sr) * FDIM + (tid & 3) * 8;
        }
    }
    const __half* wsrc = IS_G1 ? g_w1h : g_w2h;
    const __half* bptr = wsrc + (size_t)e * HDIM * FDIM
                       + (size_t)(n0 + (tid >> 2)) * KDIM + (tid & 3) * 8;
    const uint32_t dA0 = sb + OFF_A + (tid >> 2) * ROW + (tid & 3) * 16;
    const uint32_t dB0 = sb + OFF_B + (tid >> 2) * ROW + (tid & 3) * 16;

    // ---- LDSM per-lane base addresses ----
    const uint32_t a_off = sb + OFF_A + (uint32_t)(wm * 32 + (lane & 15)) * ROW
                         + ((lane >> 4) & 1) * 16;
    const uint32_t b_off = sb + OFF_B
                         + (uint32_t)(wn * WN + (lane & 7) + ((lane >> 4) & 1) * 8) * ROW
                         + ((lane >> 3) & 1) * 16;

    constexpr int NK = KDIM / BK;

    #define LOAD_TILE(T) do { \
        const int _s = (T) % NSTAGE; \
        CP16(dA0 + _s * A_ST, aptr + (T) * BK); \
        const uint32_t _db = dB0 + _s * B_ST; \
        _Pragma("unroll") \
        for (int _i = 0; _i < NBC; _i++) \
            CP16(_db + _i * (64 * ROW), bptr + (size_t)_i * 64 * KDIM + (T) * BK); \
        CP_COMMIT(); \
    } while (0)

    float acc[2][NT][4];
    #pragma unroll
    for (int mt = 0; mt < 2; mt++)
        #pragma unroll
        for (int nt = 0; nt < NT; nt++)
            #pragma unroll
            for (int i = 0; i < 4; i++) acc[mt][nt][i] = 0.f;

    LOAD_TILE(0);
    LOAD_TILE(1);
    LOAD_TILE(2);

    for (int kt = 0; kt < NK; ++kt) {
        if (kt + 3 <= NK) {
            asm volatile("cp.async.wait_group 2;" ::: "memory");
        } else if (kt + 2 == NK) {
            asm volatile("cp.async.wait_group 1;" ::: "memory");
        } else {
            asm volatile("cp.async.wait_group 0;" ::: "memory");
        }
        __syncthreads();
        if (kt + 3 < NK) LOAD_TILE(kt + 3);

        const int s = kt % NSTAGE;
        const uint32_t sA = a_off + s * A_ST;
        const uint32_t sB = b_off + s * B_ST;

        #pragma unroll
        for (int ks = 0; ks < 2; ks++) {           // two k16 steps per 32-half tile
            uint32_t a[2][4], b[NT][2];
            #pragma unroll
            for (int mt = 0; mt < 2; mt++)
                LDSM4(a[mt][0], a[mt][1], a[mt][2], a[mt][3],
                      sA + mt * (16 * ROW) + ks * 32);
            #pragma unroll
            for (int j = 0; j < NT / 2; j++)
                LDSM4(b[2 * j][0], b[2 * j][1], b[2 * j + 1][0], b[2 * j + 1][1],
                      sB + j * (16 * ROW) + ks * 32);
            #pragma unroll
            for (int mt = 0; mt < 2; mt++)
                #pragma unroll
                for (int nt = 0; nt < NT; nt++)
                    mma_f16(acc[mt][nt], a[mt], b[nt]);
        }
    }
    #undef LOAD_TILE
    __syncthreads();

    // ---- epilogue ----
    #pragma unroll
    for (int mt = 0; mt < 2; mt++) {
        #pragma unroll
        for (int half = 0; half < 2; half++) {
            const int rl = wm * 32 + mt * 16 + g + half * 8;
            const int gr = row0 + rl;
            if (gr < cnt) {
                if (IS_G1) {
                    __half* hrow = g_hbuf + (size_t)(off + gr) * FDIM + n0 + wn * WN;
                    #pragma unroll
                    for (int nt = 0; nt < NT; nt++) {
                        int c = nt * 8 + tig * 2;
                        float v0 = gelu_exact(acc[mt][nt][half * 2 + 0] + bias_s[wn * WN + c]);
                        float v1 = gelu_exact(acc[mt][nt][half * 2 + 1] + bias_s[wn * WN + c + 1]);
                        *(__half2*)(hrow + c) = __floats2half2_rn(v0, v1);
                    }
                } else {
                    const int   tok = tok_s[rl];
                    const float w   = wgt_s[rl];
                    float* orow = out + (size_t)tok * HDIM + n0 + wn * WN;
                    #pragma unroll
                    for (int nt = 0; nt < NT; nt++) {
                        int c = nt * 8 + tig * 2;
                        float v0 = w * (acc[mt][nt][half * 2 + 0] + bias_s[wn * WN + c]);
                        float v1 = w * (acc[mt][nt][half * 2 + 1] + bias_s[wn * WN + c + 1]);
                        atomicAdd(orow + c,     v0);
                        atomicAdd(orow + c + 1, v1);
                    }
                }
            }
        }
    }
}

// ---------------- launch -----------------------------------------------------
extern "C" void kernel_launch(void* const* d_in, const int* in_sizes, int n_in,
                              void* d_out, int out_size) {
    const float* x    = (const float*)d_in[0];
    const float* grad = (const float*)d_in[1];
    const float* Wr   = (const float*)d_in[2];
    const float* br   = (const float*)d_in[3];
    const float* W1   = (const float*)d_in[4];
    const float* b1   = (const float*)d_in[5];
    const float* W2   = (const float*)d_in[6];
    const float* b2   = (const float*)d_in[7];
    float* out = (float*)d_out;

    constexpr int SMEM_G1 = OFF_A + NSTAGE * A_ST + NSTAGE * (256 * ROW);  /* 104448 */
    constexpr int SMEM_G2 = OFF_A + NSTAGE * A_ST + NSTAGE * (128 * ROW);  /* 63488 */

    cudaFuncSetAttribute(moe_gemm<HDIM, 256, true>,
                         cudaFuncAttributeMaxDynamicSharedMemorySize, SMEM_G1);
    cudaFuncSetAttribute(moe_gemm<FDIM, 128, false>,
                         cudaFuncAttributeMaxDynamicSharedMemorySize, SMEM_G2);

    int nf4 = out_size / 4;
    int nzero = (nf4 + 255) / 256;

    zcnt_kernel<<<1, 32>>>();
    prep_kernel<<<PREP_XC + nzero, 256>>>(x, grad, Wr, br, W1, W2, (float4*)out, nf4);
    prefix_kernel<<<1, 32>>>();

    moe_gemm<HDIM, 256, true>
        <<<dim3(FDIM / 256, NTOK / BM, NEXP), 256, SMEM_G1>>>(b1, nullptr);
    moe_gemm<FDIM, 128, false>
        <<<dim3(HDIM / 128, NTOK / BM, NEXP), 256, SMEM_G2>>>(b2, out);
}